// round 15
// baseline (speedup 1.0000x reference)
#include <cuda_runtime.h>
#include <cstdint>

// ---------------------------------------------------------------------------
// MemoryAttention R15: R14 + latency-hoisted select/hm2 loads.
//   - select loads f[0..3] (prev chunk's score rows) + lmax and the hm2 quad
//     load are issued BEFORE the GEMM; their LDS latency hides under
//     LDSM/MMA. Ballot-driven insert processing stays after the GEMM.
//   - scores computed in place in acc (v-staging regs eliminated to keep
//     register pressure at <=128, no spill).
//   - everything else identical to R14 (32q x 16c warp tile, dedup LDSM,
//     TMA blob, 1 barrier/chunk, exact fp32 rescore epilogue).
// ---------------------------------------------------------------------------

#define FULLMASK 0xffffffffu

constexpr int NQ  = 8192;
constexpr int NC  = 32768;
constexpr int DK  = 64;
constexpr int QT  = 32;        // queries per CTA
constexpr int CT  = 128;       // centers per chunk
constexpr int NCHUNK = NC / CT;    // 256
constexpr int MUS  = 68;       // mu row stride (floats) inside blob
constexpr int SSTR = 132;      // score row stride
constexpr int SBUF = QT * SSTR;    // floats per score buffer
constexpr int BUFFLOATS = CT + CT * MUS;      // 128 hm2 + 8704 mu = 8832
constexpr uint32_t BUFBYTES = BUFFLOATS * 4;  // 35328 B

static __device__ float g_hm2[NC];
static __device__ float g_blob[(size_t)NCHUNK * BUFFLOATS];   // ~9 MB

constexpr int RV_OFF = 0;
constexpr int RE_OFF = NQ * 128;
constexpr int G_OFF  = RE_OFF + NQ * 4;

// smem layout (floats)
constexpr int OFF_MBAR = 0;                        // 2 mbarriers
constexpr int OFF_BLOB = 16;                       // 2*8832 = 17664
constexpr int OFF_S0   = OFF_BLOB + 2 * BUFFLOATS; // 4224 (sQ aliases here)
constexpr int OFF_S1   = OFF_S0 + SBUF;            // 4224
constexpr int OFF_SCR  = OFF_S1 + SBUF;            // 512
constexpr int SMEM_FLOATS = OFF_SCR + 8 * 64;      // 26640 f = 106560 B

__device__ __forceinline__ uint32_t to_tf32(float f) {
    uint32_t u;
    asm("cvt.rna.tf32.f32 %0, %1;" : "=r"(u) : "f"(f));
    return u;
}

__global__ void prep_kernel(const float* __restrict__ mu) {
    int c = blockIdx.x * 256 + threadIdx.x;   // 32768 rows
    const float4* r = reinterpret_cast<const float4*>(mu) + (size_t)c * 16;
    int n = c & 127;
    float* blob = g_blob + (size_t)(c >> 7) * BUFFLOATS;
    float4* w4 = reinterpret_cast<float4*>(blob + CT + n * MUS);
    float s = 0.f;
#pragma unroll
    for (int j = 0; j < 16; j++) {
        float4 v = r[j];
        s += v.x * v.x + v.y * v.y + v.z * v.z + v.w * v.w;
        float4 t;
        t.x = __uint_as_float(to_tf32(v.x));
        t.y = __uint_as_float(to_tf32(v.y));
        t.z = __uint_as_float(to_tf32(v.z));
        t.w = __uint_as_float(to_tf32(v.w));
        w4[j] = t;
    }
    // hm2 quad layout: thread (w,tc) reads float4 =
    //   { hm2[16w+2tc], hm2[16w+2tc+1], hm2[16w+8+2tc], hm2[16w+8+2tc+1] }
    int w  = n >> 4, inner = n & 15;
    int h  = inner >> 3, rem = inner & 7;
    int tc = rem >> 1, e = rem & 1;
    blob[(w * 4 + tc) * 4 + 2 * h + e] = 0.5f * s;
    g_hm2[c] = 0.5f * s;
}

__device__ __forceinline__ unsigned fenc(float f) {
    unsigned u = __float_as_uint(f);
    return (u & 0x80000000u) ? ~u : (u | 0x80000000u);
}
__device__ __forceinline__ float fdec(unsigned u) {
    return (u & 0x80000000u) ? __uint_as_float(u & 0x7fffffffu)
                             : __uint_as_float(~u);
}
__device__ __forceinline__ unsigned redux_min_u32(unsigned v) {
    unsigned r;
    asm("redux.sync.min.u32 %0, %1, 0xffffffff;" : "=r"(r) : "r"(v));
    return r;
}
__device__ __forceinline__ void mma_tf32(float* d, const uint32_t* a,
                                         uint32_t b0, uint32_t b1) {
    asm("mma.sync.aligned.m16n8k8.row.col.f32.tf32.tf32.f32 "
        "{%0,%1,%2,%3}, {%4,%5,%6,%7}, {%8,%9}, {%0,%1,%2,%3};"
        : "+f"(d[0]), "+f"(d[1]), "+f"(d[2]), "+f"(d[3])
        : "r"(a[0]), "r"(a[1]), "r"(a[2]), "r"(a[3]), "r"(b0), "r"(b1));
}
__device__ __forceinline__ void ldsm_x4(uint32_t addr, uint32_t& r0,
                                        uint32_t& r1, uint32_t& r2, uint32_t& r3) {
    asm volatile("ldmatrix.sync.aligned.m8n8.x4.shared.b16 {%0,%1,%2,%3}, [%4];"
                 : "=r"(r0), "=r"(r1), "=r"(r2), "=r"(r3) : "r"(addr));
}
__device__ __forceinline__ void mbar_init(uint32_t addr, uint32_t count) {
    asm volatile("mbarrier.init.shared.b64 [%0], %1;" :: "r"(addr), "r"(count)
                 : "memory");
}
__device__ __forceinline__ void mbar_expect_tx(uint32_t addr, uint32_t bytes) {
    asm volatile("mbarrier.arrive.expect_tx.shared.b64 _, [%0], %1;"
                 :: "r"(addr), "r"(bytes) : "memory");
}
__device__ __forceinline__ void mbar_wait(uint32_t addr, uint32_t parity) {
    asm volatile(
        "{\n\t"
        ".reg .pred P;\n"
        "W_%=:\n\t"
        "mbarrier.try_wait.parity.acquire.cta.shared::cta.b64 P, [%0], %1, 0x989680;\n\t"
        "@P bra D_%=;\n\t"
        "bra W_%=;\n"
        "D_%=:\n\t"
        "}"
        :: "r"(addr), "r"(parity) : "memory");
}
__device__ __forceinline__ void bulk_g2s(uint32_t dst, const void* src,
                                         uint32_t bytes, uint32_t mbar) {
    asm volatile(
        "cp.async.bulk.shared::cta.global.mbarrier::complete_tx::bytes "
        "[%0], [%1], %2, [%3];"
        :: "r"(dst), "l"(src), "r"(bytes), "r"(mbar) : "memory");
}

__global__ __launch_bounds__(256, 2)
void ma_kernel(const float* __restrict__ x,
               const float* __restrict__ q_tilde,
               const float* __restrict__ g_prior,
               const float* __restrict__ mu,
               const float* __restrict__ V,
               const float* __restrict__ E,
               const float* __restrict__ sig,
               const float* __restrict__ Wg,
               const float* __restrict__ Wgb,
               const float* __restrict__ gpw,
               float* __restrict__ out) {
    extern __shared__ float sm[];
    float* sBlob = sm + OFF_BLOB;
    float* sS    = sm + OFF_S0;     // two score buffers
    float* sQ    = sm + OFF_S0;     // alias: Q staged here only for A-frags
    float* sScr  = sm + OFF_SCR;

    const int tid  = threadIdx.x;
    const int lane = tid & 31;
    const int wid  = tid >> 5;      // warp = column block w (16 cols)
    const int q0   = blockIdx.x * QT;

    const int tr = lane >> 2;     // 0..7
    const int tc = lane & 3;      // 0..3

    const uint32_t smemBase = (uint32_t)__cvta_generic_to_shared(sm);
    const uint32_t mbarA  = smemBase + OFF_MBAR * 4;
    const uint32_t sblobA = smemBase + OFF_BLOB * 4;

    // ldmatrix lane offset (bytes) within a blob: rows 16*wid..+15, k lo/hi
    const uint32_t boff = (uint32_t)(CT * 4) +
        (uint32_t)(((16 * wid + ((lane >> 4) & 1) * 8 + (lane & 7)) * MUS
                    + ((lane >> 3) & 1) * 4) * 4);

    // hm2 quad word offset
    const int hmoff = 16 * wid + 4 * tc;

    // score store word offsets for the 4 rows R = 16m+8h+tr
    int Wr[2][2];
#pragma unroll
    for (int m = 0; m < 2; m++)
#pragma unroll
        for (int h = 0; h < 2; h++) {
            int R = 16 * m + 8 * h + tr;
            Wr[m][h] = (16 * (wid ^ (R & 1)) + 4 * tc + 2048 - 4 * R) & 127;
        }

    auto issue_chunk = [&](int chunk) {
        if (tid == 0) {
            int buf = chunk & 1;
            uint32_t mb = mbarA + (uint32_t)(buf * 8);
            mbar_expect_tx(mb, BUFBYTES);
            bulk_g2s(sblobA + (uint32_t)buf * BUFBYTES,
                     g_blob + (size_t)chunk * BUFFLOATS, BUFBYTES, mb);
        }
    };

    // ---- prologue: stage Q (aliased region), init mbarriers ----
    for (int idx = tid; idx < QT * DK; idx += 256) {
        int q = idx >> 6, k = idx & 63;
        sQ[q * MUS + k] = q_tilde[(size_t)(q0 + q) * DK + k];
    }
    if (tid == 0) {
        mbar_init(mbarA, 1);
        mbar_init(mbarA + 8, 1);
    }
    __syncthreads();   // sQ + mbarrier init visible
    issue_chunk(0);

    // A fragments for BOTH m-tiles (rows 16m+tr / +8), resident all chunks
    uint32_t af[2][8][4];
#pragma unroll
    for (int m = 0; m < 2; m++) {
        const float* qa = sQ + (16 * m + tr) * MUS + tc;
#pragma unroll
        for (int kt = 0; kt < 8; kt++) {
            af[m][kt][0] = to_tf32(qa[8 * kt]);
            af[m][kt][1] = to_tf32(qa[8 * MUS + 8 * kt]);
            af[m][kt][2] = to_tf32(qa[8 * kt + 4]);
            af[m][kt][3] = to_tf32(qa[8 * MUS + 8 * kt + 4]);
        }
    }
    // sQ dead from here; first sS0 write is after the first in-loop barrier.

    // selection state: warp wid owns queries 4*wid + r
    unsigned cu[4]; int ci[4]; float thr[4]; unsigned thrU[4];
    const unsigned NEGINF_U = fenc(-INFINITY);
#pragma unroll
    for (int r = 0; r < 4; r++) {
        cu[r] = NEGINF_U; ci[r] = 0; thr[r] = -INFINITY; thrU[r] = NEGINF_U;
    }

    // select processing (ballot phase) given preloaded rows f[] and lmax[]
    auto select_process = [&](const float4* f, const float* lmax, int base) {
        bool anyc = (lmax[0] > thr[0]) | (lmax[1] > thr[1]) |
                    (lmax[2] > thr[2]) | (lmax[3] > thr[3]);
        if (!__ballot_sync(FULLMASK, anyc)) return;
#pragma unroll
        for (int r = 0; r < 4; r++) {
            const int row = 4 * wid + r;
            unsigned m = __ballot_sync(FULLMASK, lmax[r] > thr[r]);
            while (m) {
                int src = __ffs(m) - 1;
                m &= m - 1;
                float g0 = __shfl_sync(FULLMASK, f[r].x, src);
                float g1 = __shfl_sync(FULLMASK, f[r].y, src);
                float g2 = __shfl_sync(FULLMASK, f[r].z, src);
                float g3 = __shfl_sync(FULLMASK, f[r].w, src);
                // decode stored column: X=(4src+4row)&127; w=(X>>4)^(row&1)
                int X = (4 * src + 4 * row) & 127;
                int wdec = ((X >> 4) ^ (row & 1));
                int colb = 16 * wdec + ((X >> 2) & 3) * 2;
                int ib = base + colb;
#pragma unroll
                for (int j = 0; j < 4; j++) {
                    float nv = (j == 0) ? g0 : (j == 1) ? g1 : (j == 2) ? g2 : g3;
                    if (nv > thr[r]) {
                        unsigned bl = __ballot_sync(FULLMASK, cu[r] == thrU[r]);
                        int ml = __ffs(bl) - 1;
                        if (lane == ml) {
                            cu[r] = fenc(nv);
                            ci[r] = ib + 8 * (j >> 1) + (j & 1);
                        }
                        thrU[r] = redux_min_u32(cu[r]);
                        thr[r]  = fdec(thrU[r]);
                    }
                }
            }
        }
    };

    for (int ch = 0; ch < NCHUNK; ++ch) {
        const int buf = ch & 1;
        mbar_wait(mbarA + (uint32_t)(buf * 8), (ch >> 1) & 1);
        __syncthreads();   // buffer visible; stores(ch-1), select(ch-2) done;
                           // GEMM(ch-1) reads of mu[(ch+1)&1] done
        if (ch + 1 < NCHUNK) issue_chunk(ch + 1);

        const uint32_t bufB = sblobA + (uint32_t)buf * BUFBYTES;
        const float*   hbp  = sBlob + buf * BUFFLOATS;

        // ---- hoisted loads: select rows (prev chunk) + hm2 quad ----
        // Their LDS latency is hidden under the GEMM below.
        float4 f[4]; float lmax[4];
        if (ch > 0) {
            const float* sbuf = sS + ((ch - 1) & 1) * SBUF;
#pragma unroll
            for (int r = 0; r < 4; r++) {
                f[r] = *reinterpret_cast<const float4*>(
                           sbuf + (4 * wid + r) * SSTR + 4 * lane);
                lmax[r] = fmaxf(fmaxf(f[r].x, f[r].y), fmaxf(f[r].z, f[r].w));
            }
        }
        float4 hm = *reinterpret_cast<const float4*>(hbp + hmoff);

        // ---- tensor-core GEMM: warp tile 32q x 16c ----
        float acc[2][2][4];
#pragma unroll
        for (int m = 0; m < 2; m++)
#pragma unroll
            for (int nt = 0; nt < 2; nt++)
#pragma unroll
                for (int j = 0; j < 4; j++) acc[m][nt][j] = 0.f;

        const uint32_t a0 = bufB + boff;
#pragma unroll
        for (int kt = 0; kt < 8; kt++) {
            uint32_t r0, r1, r2, r3;
            ldsm_x4(a0 + kt * 32, r0, r1, r2, r3);
            mma_tf32(acc[0][0], af[0][kt], r0, r1);
            mma_tf32(acc[0][1], af[0][kt], r2, r3);
            mma_tf32(acc[1][0], af[1][kt], r0, r1);
            mma_tf32(acc[1][1], af[1][kt], r2, r3);
        }

        // ---- deferred selection processing (loads already in flight) ----
        if (ch > 0)
            select_process(f, lmax, (ch - 1) * CT);

        // ---- scores in place -> sS[ch&1] (row-shifted layout) ----
        {
            float* sb = sS + buf * SBUF;
#pragma unroll
            for (int m = 0; m < 2; m++) {
#pragma unroll
                for (int nt = 0; nt < 2; nt++) {
                    acc[m][nt][0] -= (nt ? hm.z : hm.x);
                    acc[m][nt][1] -= (nt ? hm.w : hm.y);
                    acc[m][nt][2] -= (nt ? hm.z : hm.x);
                    acc[m][nt][3] -= (nt ? hm.w : hm.y);
                }
#pragma unroll
                for (int h = 0; h < 2; h++) {
                    int R = 16 * m + 8 * h + tr;
                    float4 v;
                    v.x = acc[m][0][2 * h];
                    v.y = acc[m][0][2 * h + 1];
                    v.z = acc[m][1][2 * h];
                    v.w = acc[m][1][2 * h + 1];
                    *reinterpret_cast<float4*>(sb + R * SSTR + Wr[m][h]) = v;
                }
            }
        }
    }

    // final chunk's selection
    __syncthreads();
    {
        const float* sbuf = sS + ((NCHUNK - 1) & 1) * SBUF;
        float4 f[4]; float lmax[4];
#pragma unroll
        for (int r = 0; r < 4; r++) {
            f[r] = *reinterpret_cast<const float4*>(
                       sbuf + (4 * wid + r) * SSTR + 4 * lane);
            lmax[r] = fmaxf(fmaxf(f[r].x, f[r].y), fmaxf(f[r].z, f[r].w));
        }
        select_process(f, lmax, (NCHUNK - 1) * CT);
    }

    // publish top-32 indices per query into sS0 (final select read sS1)
    int* sTopI = reinterpret_cast<int*>(sS);
#pragma unroll
    for (int r = 0; r < 4; r++) {
        int q = 4 * wid + r;
        sTopI[q * 32 + lane] = ci[r];
    }
    __syncthreads();

    const float sigma  = sig[0];
    const float inv_s2 = 1.f / (sigma * sigma);
    const float bgate  = Wgb[0];
    const float gw     = gpw[0];

    float* myW = sScr + wid * 64;
    int*   myI = reinterpret_cast<int*>(myW + 32);

    // ---- epilogue: EXACT rescore + softmax + gathers + gate ----
#pragma unroll
    for (int round = 0; round < 4; ++round) {
        int q   = wid + 8 * round;
        int qg2 = q0 + q;

        int idx = sTopI[q * 32 + lane];

        const float4* mrow = reinterpret_cast<const float4*>(mu + (size_t)idx * DK);
        const float4* qrow = reinterpret_cast<const float4*>(q_tilde + (size_t)qg2 * DK);
        float d0 = 0.f, d1 = 0.f, d2 = 0.f, d3 = 0.f;
#pragma unroll
        for (int j = 0; j < 16; j += 4) {
            float4 m0 = mrow[j],     qv0 = qrow[j];
            float4 m1 = mrow[j + 1], qv1 = qrow[j + 1];
            float4 m2 = mrow[j + 2], qv2 = qrow[j + 2];
            float4 m3 = mrow[j + 3], qv3 = qrow[j + 3];
            d0 += m0.x * qv0.x + m0.y * qv0.y + m0.z * qv0.z + m0.w * qv0.w;
            d1 += m1.x * qv1.x + m1.y * qv1.y + m1.z * qv1.z + m1.w * qv1.w;
            d2 += m2.x * qv2.x + m2.y * qv2.y + m2.z * qv2.z + m2.w * qv2.w;
            d3 += m3.x * qv3.x + m3.y * qv3.y + m3.z * qv3.z + m3.w * qv3.w;
        }
        float s = ((d0 + d1) + (d2 + d3) - g_hm2[idx]) * inv_s2;

        float mx = s;
#pragma unroll
        for (int off = 16; off; off >>= 1)
            mx = fmaxf(mx, __shfl_xor_sync(FULLMASK, mx, off));
        float e = __expf(s - mx);
        float se = e;
#pragma unroll
        for (int off = 16; off; off >>= 1)
            se += __shfl_xor_sync(FULLMASK, se, off);
        float wgt = e / se;

        myW[lane] = wgt;
        myI[lane] = idx;
        __syncwarp();

        float4 acc = make_float4(0.f, 0.f, 0.f, 0.f);
#pragma unroll 4
        for (int k = 0; k < 32; k++) {
            float wk = myW[k];
            size_t row = (size_t)myI[k];
            float4 v = reinterpret_cast<const float4*>(V + row * 128)[lane];
            acc.x += wk * v.x; acc.y += wk * v.y;
            acc.z += wk * v.z; acc.w += wk * v.w;
        }

        float re = 0.f;
        if (lane < 4) {
            for (int k = 0; k < 32; k++)
                re += myW[k] * E[(size_t)myI[k] * 4 + lane];
        }

        const float4 wv = reinterpret_cast<const float4*>(Wg + 256)[lane];
        float tot = acc.x * wv.x + acc.y * wv.y + acc.z * wv.z + acc.w * wv.w;
        const float* xq = x + (size_t)qg2 * 256;
#pragma unroll
        for (int u = 0; u < 8; u++) {
            int t = lane + 32 * u;
            tot += xq[t] * Wg[t];
        }
#pragma unroll
        for (int off = 16; off; off >>= 1)
            tot += __shfl_xor_sync(FULLMASK, tot, off);

        reinterpret_cast<float4*>(out + RV_OFF + (size_t)qg2 * 128)[lane] = acc;
        if (lane < 4) out[RE_OFF + (size_t)qg2 * 4 + lane] = re;
        if (lane == 0) {
            float z = tot + bgate + gw * g_prior[qg2];
            out[G_OFF + qg2] = 1.f / (1.f + __expf(-z));
        }
        __syncwarp();
    }
}

extern "C" void kernel_launch(void* const* d_in, const int* in_sizes, int n_in,
                              void* d_out, int out_size) {
    (void)in_sizes; (void)n_in; (void)out_size;
    const float* x   = (const float*)d_in[0];
    const float* qt  = (const float*)d_in[1];
    const float* gp  = (const float*)d_in[2];
    const float* mu  = (const float*)d_in[3];
    const float* V   = (const float*)d_in[4];
    const float* E   = (const float*)d_in[5];
    const float* sg  = (const float*)d_in[6];
    const float* Wg  = (const float*)d_in[7];
    const float* Wb  = (const float*)d_in[8];
    const float* gw  = (const float*)d_in[9];

    prep_kernel<<<NC / 256, 256>>>(mu);

    const int smem_bytes = SMEM_FLOATS * 4;   // 106560
    cudaFuncSetAttribute(ma_kernel, cudaFuncAttributeMaxDynamicSharedMemorySize,
                         smem_bytes);
    ma_kernel<<<NQ / QT, 256, smem_bytes>>>(x, qt, gp, mu, V, E, sg, Wg, Wb, gw,
                                            (float*)d_out);
}

// round 16
// speedup vs baseline: 1.1349x; 1.1349x over previous
#include <cuda_runtime.h>
#include <cstdint>

// ---------------------------------------------------------------------------
// MemoryAttention R16: R14 (best: 480.7us) + TMA issue reordered ahead of the
// completion wait.
//   Loop top was: mbar_wait(ch) -> syncthreads -> issue TMA(ch+1)   (serial)
//   Now:          syncthreads -> issue TMA(ch+1) -> mbar_wait(ch)   (overlap)
//   The barrier alone orders all warps' GEMM(ch-1) reads of the target
//   buffer, so issuing before the wait is race-free; TMA(ch+1) now flies
//   during GEMM(ch) instead of after TMA(ch) completes.
//   R15's register-hoisting is fully reverted (it regressed: +regs across
//   the MMA region serialized the GEMM).
// ---------------------------------------------------------------------------

#define FULLMASK 0xffffffffu

constexpr int NQ  = 8192;
constexpr int NC  = 32768;
constexpr int DK  = 64;
constexpr int QT  = 32;        // queries per CTA
constexpr int CT  = 128;       // centers per chunk
constexpr int NCHUNK = NC / CT;    // 256
constexpr int MUS  = 68;       // mu row stride (floats) inside blob
constexpr int SSTR = 132;      // score row stride
constexpr int SBUF = QT * SSTR;    // floats per score buffer
constexpr int BUFFLOATS = CT + CT * MUS;      // 128 hm2 + 8704 mu = 8832
constexpr uint32_t BUFBYTES = BUFFLOATS * 4;  // 35328 B

static __device__ float g_hm2[NC];
static __device__ float g_blob[(size_t)NCHUNK * BUFFLOATS];   // ~9 MB

constexpr int RV_OFF = 0;
constexpr int RE_OFF = NQ * 128;
constexpr int G_OFF  = RE_OFF + NQ * 4;

// smem layout (floats)
constexpr int OFF_MBAR = 0;                        // 2 mbarriers
constexpr int OFF_BLOB = 16;                       // 2*8832 = 17664
constexpr int OFF_S0   = OFF_BLOB + 2 * BUFFLOATS; // 4224 (sQ aliases here)
constexpr int OFF_S1   = OFF_S0 + SBUF;            // 4224
constexpr int OFF_SCR  = OFF_S1 + SBUF;            // 512
constexpr int SMEM_FLOATS = OFF_SCR + 8 * 64;      // 26640 f = 106560 B

__device__ __forceinline__ uint32_t to_tf32(float f) {
    uint32_t u;
    asm("cvt.rna.tf32.f32 %0, %1;" : "=r"(u) : "f"(f));
    return u;
}

__global__ void prep_kernel(const float* __restrict__ mu) {
    int c = blockIdx.x * 256 + threadIdx.x;   // 32768 rows
    const float4* r = reinterpret_cast<const float4*>(mu) + (size_t)c * 16;
    int n = c & 127;
    float* blob = g_blob + (size_t)(c >> 7) * BUFFLOATS;
    float4* w4 = reinterpret_cast<float4*>(blob + CT + n * MUS);
    float s = 0.f;
#pragma unroll
    for (int j = 0; j < 16; j++) {
        float4 v = r[j];
        s += v.x * v.x + v.y * v.y + v.z * v.z + v.w * v.w;
        float4 t;
        t.x = __uint_as_float(to_tf32(v.x));
        t.y = __uint_as_float(to_tf32(v.y));
        t.z = __uint_as_float(to_tf32(v.z));
        t.w = __uint_as_float(to_tf32(v.w));
        w4[j] = t;
    }
    // hm2 quad layout: thread (w,tc) reads float4 =
    //   { hm2[16w+2tc], hm2[16w+2tc+1], hm2[16w+8+2tc], hm2[16w+8+2tc+1] }
    int w  = n >> 4, inner = n & 15;
    int h  = inner >> 3, rem = inner & 7;
    int tc = rem >> 1, e = rem & 1;
    blob[(w * 4 + tc) * 4 + 2 * h + e] = 0.5f * s;
    g_hm2[c] = 0.5f * s;
}

__device__ __forceinline__ unsigned fenc(float f) {
    unsigned u = __float_as_uint(f);
    return (u & 0x80000000u) ? ~u : (u | 0x80000000u);
}
__device__ __forceinline__ float fdec(unsigned u) {
    return (u & 0x80000000u) ? __uint_as_float(u & 0x7fffffffu)
                             : __uint_as_float(~u);
}
__device__ __forceinline__ unsigned redux_min_u32(unsigned v) {
    unsigned r;
    asm("redux.sync.min.u32 %0, %1, 0xffffffff;" : "=r"(r) : "r"(v));
    return r;
}
__device__ __forceinline__ void mma_tf32(float* d, const uint32_t* a,
                                         uint32_t b0, uint32_t b1) {
    asm("mma.sync.aligned.m16n8k8.row.col.f32.tf32.tf32.f32 "
        "{%0,%1,%2,%3}, {%4,%5,%6,%7}, {%8,%9}, {%0,%1,%2,%3};"
        : "+f"(d[0]), "+f"(d[1]), "+f"(d[2]), "+f"(d[3])
        : "r"(a[0]), "r"(a[1]), "r"(a[2]), "r"(a[3]), "r"(b0), "r"(b1));
}
__device__ __forceinline__ void ldsm_x4(uint32_t addr, uint32_t& r0,
                                        uint32_t& r1, uint32_t& r2, uint32_t& r3) {
    asm volatile("ldmatrix.sync.aligned.m8n8.x4.shared.b16 {%0,%1,%2,%3}, [%4];"
                 : "=r"(r0), "=r"(r1), "=r"(r2), "=r"(r3) : "r"(addr));
}
__device__ __forceinline__ void mbar_init(uint32_t addr, uint32_t count) {
    asm volatile("mbarrier.init.shared.b64 [%0], %1;" :: "r"(addr), "r"(count)
                 : "memory");
}
__device__ __forceinline__ void mbar_expect_tx(uint32_t addr, uint32_t bytes) {
    asm volatile("mbarrier.arrive.expect_tx.shared.b64 _, [%0], %1;"
                 :: "r"(addr), "r"(bytes) : "memory");
}
__device__ __forceinline__ void mbar_wait(uint32_t addr, uint32_t parity) {
    asm volatile(
        "{\n\t"
        ".reg .pred P;\n"
        "W_%=:\n\t"
        "mbarrier.try_wait.parity.acquire.cta.shared::cta.b64 P, [%0], %1, 0x989680;\n\t"
        "@P bra D_%=;\n\t"
        "bra W_%=;\n"
        "D_%=:\n\t"
        "}"
        :: "r"(addr), "r"(parity) : "memory");
}
__device__ __forceinline__ void bulk_g2s(uint32_t dst, const void* src,
                                         uint32_t bytes, uint32_t mbar) {
    asm volatile(
        "cp.async.bulk.shared::cta.global.mbarrier::complete_tx::bytes "
        "[%0], [%1], %2, [%3];"
        :: "r"(dst), "l"(src), "r"(bytes), "r"(mbar) : "memory");
}

__global__ __launch_bounds__(256, 2)
void ma_kernel(const float* __restrict__ x,
               const float* __restrict__ q_tilde,
               const float* __restrict__ g_prior,
               const float* __restrict__ mu,
               const float* __restrict__ V,
               const float* __restrict__ E,
               const float* __restrict__ sig,
               const float* __restrict__ Wg,
               const float* __restrict__ Wgb,
               const float* __restrict__ gpw,
               float* __restrict__ out) {
    extern __shared__ float sm[];
    float* sBlob = sm + OFF_BLOB;
    float* sS    = sm + OFF_S0;     // two score buffers
    float* sQ    = sm + OFF_S0;     // alias: Q staged here only for A-frags
    float* sScr  = sm + OFF_SCR;

    const int tid  = threadIdx.x;
    const int lane = tid & 31;
    const int wid  = tid >> 5;      // warp = column block w (16 cols)
    const int q0   = blockIdx.x * QT;

    const int tr = lane >> 2;     // 0..7
    const int tc = lane & 3;      // 0..3

    const uint32_t smemBase = (uint32_t)__cvta_generic_to_shared(sm);
    const uint32_t mbarA  = smemBase + OFF_MBAR * 4;
    const uint32_t sblobA = smemBase + OFF_BLOB * 4;

    // ldmatrix lane offset (bytes) within a blob: rows 16*wid..+15, k lo/hi
    const uint32_t boff = (uint32_t)(CT * 4) +
        (uint32_t)(((16 * wid + ((lane >> 4) & 1) * 8 + (lane & 7)) * MUS
                    + ((lane >> 3) & 1) * 4) * 4);

    // hm2 quad word offset
    const int hmoff = 16 * wid + 4 * tc;

    // score store word offsets for the 4 rows R = 16m+8h+tr
    int Wr[2][2];
#pragma unroll
    for (int m = 0; m < 2; m++)
#pragma unroll
        for (int h = 0; h < 2; h++) {
            int R = 16 * m + 8 * h + tr;
            Wr[m][h] = (16 * (wid ^ (R & 1)) + 4 * tc + 2048 - 4 * R) & 127;
        }

    auto issue_chunk = [&](int chunk) {
        if (tid == 0) {
            int buf = chunk & 1;
            uint32_t mb = mbarA + (uint32_t)(buf * 8);
            mbar_expect_tx(mb, BUFBYTES);
            bulk_g2s(sblobA + (uint32_t)buf * BUFBYTES,
                     g_blob + (size_t)chunk * BUFFLOATS, BUFBYTES, mb);
        }
    };

    // ---- prologue: stage Q (aliased region), init mbarriers ----
    for (int idx = tid; idx < QT * DK; idx += 256) {
        int q = idx >> 6, k = idx & 63;
        sQ[q * MUS + k] = q_tilde[(size_t)(q0 + q) * DK + k];
    }
    if (tid == 0) {
        mbar_init(mbarA, 1);
        mbar_init(mbarA + 8, 1);
    }
    __syncthreads();   // sQ + mbarrier init visible
    issue_chunk(0);

    // A fragments for BOTH m-tiles (rows 16m+tr / +8), resident all chunks
    uint32_t af[2][8][4];
#pragma unroll
    for (int m = 0; m < 2; m++) {
        const float* qa = sQ + (16 * m + tr) * MUS + tc;
#pragma unroll
        for (int kt = 0; kt < 8; kt++) {
            af[m][kt][0] = to_tf32(qa[8 * kt]);
            af[m][kt][1] = to_tf32(qa[8 * MUS + 8 * kt]);
            af[m][kt][2] = to_tf32(qa[8 * kt + 4]);
            af[m][kt][3] = to_tf32(qa[8 * MUS + 8 * kt + 4]);
        }
    }
    // sQ dead from here; first sS0 write is after the first in-loop barrier.

    // selection state: warp wid owns queries 4*wid + r
    unsigned cu[4]; int ci[4]; float thr[4]; unsigned thrU[4];
    const unsigned NEGINF_U = fenc(-INFINITY);
#pragma unroll
    for (int r = 0; r < 4; r++) {
        cu[r] = NEGINF_U; ci[r] = 0; thr[r] = -INFINITY; thrU[r] = NEGINF_U;
    }

    // deferred selection of one chunk's score tile (reads sbuf)
    auto select_chunk = [&](const float* sbuf, int base) {
        float4 f[4]; float lmax[4];
#pragma unroll
        for (int r = 0; r < 4; r++) {
            const float* row = sbuf + (4 * wid + r) * SSTR;
            f[r] = *reinterpret_cast<const float4*>(row + 4 * lane);
            lmax[r] = fmaxf(fmaxf(f[r].x, f[r].y), fmaxf(f[r].z, f[r].w));
        }
        bool anyc = (lmax[0] > thr[0]) | (lmax[1] > thr[1]) |
                    (lmax[2] > thr[2]) | (lmax[3] > thr[3]);
        if (!__ballot_sync(FULLMASK, anyc)) return;
#pragma unroll
        for (int r = 0; r < 4; r++) {
            const int row = 4 * wid + r;
            unsigned m = __ballot_sync(FULLMASK, lmax[r] > thr[r]);
            while (m) {
                int src = __ffs(m) - 1;
                m &= m - 1;
                float g0 = __shfl_sync(FULLMASK, f[r].x, src);
                float g1 = __shfl_sync(FULLMASK, f[r].y, src);
                float g2 = __shfl_sync(FULLMASK, f[r].z, src);
                float g3 = __shfl_sync(FULLMASK, f[r].w, src);
                // decode stored column: X=(4src+4row)&127; w=(X>>4)^(row&1)
                int X = (4 * src + 4 * row) & 127;
                int wdec = ((X >> 4) ^ (row & 1));
                int colb = 16 * wdec + ((X >> 2) & 3) * 2;
                int ib = base + colb;
#pragma unroll
                for (int j = 0; j < 4; j++) {
                    float nv = (j == 0) ? g0 : (j == 1) ? g1 : (j == 2) ? g2 : g3;
                    if (nv > thr[r]) {
                        unsigned bl = __ballot_sync(FULLMASK, cu[r] == thrU[r]);
                        int ml = __ffs(bl) - 1;
                        if (lane == ml) {
                            cu[r] = fenc(nv);
                            ci[r] = ib + 8 * (j >> 1) + (j & 1);
                        }
                        thrU[r] = redux_min_u32(cu[r]);
                        thr[r]  = fdec(thrU[r]);
                    }
                }
            }
        }
    };

    for (int ch = 0; ch < NCHUNK; ++ch) {
        const int buf = ch & 1;
        // R16 reorder: barrier FIRST (orders stores(ch-1), select(ch-2), and
        // all warps' GEMM(ch-1) reads of buffer buf^1), then issue TMA(ch+1)
        // into buffer buf^1 (now provably free), THEN wait for chunk ch.
        // TMA(ch+1) is in flight during GEMM(ch) instead of being serialized
        // behind TMA(ch)'s completion.
        __syncthreads();
        if (ch + 1 < NCHUNK) issue_chunk(ch + 1);
        mbar_wait(mbarA + (uint32_t)(buf * 8), (ch >> 1) & 1);

        const uint32_t bufB = sblobA + (uint32_t)buf * BUFBYTES;
        const float*   hbp  = sBlob + buf * BUFFLOATS;

        // ---- tensor-core GEMM: warp tile 32q x 16c ----
        float acc[2][2][4];
#pragma unroll
        for (int m = 0; m < 2; m++)
#pragma unroll
            for (int nt = 0; nt < 2; nt++)
#pragma unroll
                for (int j = 0; j < 4; j++) acc[m][nt][j] = 0.f;

        const uint32_t a0 = bufB + boff;
#pragma unroll
        for (int kt = 0; kt < 8; kt++) {
            uint32_t r0, r1, r2, r3;
            ldsm_x4(a0 + kt * 32, r0, r1, r2, r3);
            mma_tf32(acc[0][0], af[0][kt], r0, r1);
            mma_tf32(acc[0][1], af[0][kt], r2, r3);
            mma_tf32(acc[1][0], af[1][kt], r0, r1);
            mma_tf32(acc[1][1], af[1][kt], r2, r3);
        }

        // ---- deferred selection of previous chunk (overlaps GEMM latency) ----
        if (ch > 0)
            select_chunk(sS + ((ch - 1) & 1) * SBUF, (ch - 1) * CT);

        // ---- scores -> sS[ch&1] (row-shifted layout, 4x STS.128) ----
        {
            float* sb = sS + buf * SBUF;
            float4 hm = *reinterpret_cast<const float4*>(hbp + hmoff);
#pragma unroll
            for (int m = 0; m < 2; m++)
#pragma unroll
                for (int h = 0; h < 2; h++) {
                    int R = 16 * m + 8 * h + tr;
                    float4 v;
                    v.x = acc[m][0][2 * h]     - hm.x;
                    v.y = acc[m][0][2 * h + 1] - hm.y;
                    v.z = acc[m][1][2 * h]     - hm.z;
                    v.w = acc[m][1][2 * h + 1] - hm.w;
                    *reinterpret_cast<float4*>(sb + R * SSTR + Wr[m][h]) = v;
                }
        }
    }

    // final chunk's selection
    __syncthreads();
    select_chunk(sS + ((NCHUNK - 1) & 1) * SBUF, (NCHUNK - 1) * CT);

    // publish top-32 indices per query into sS0 (final select read sS1)
    int* sTopI = reinterpret_cast<int*>(sS);
#pragma unroll
    for (int r = 0; r < 4; r++) {
        int q = 4 * wid + r;
        sTopI[q * 32 + lane] = ci[r];
    }
    __syncthreads();

    const float sigma  = sig[0];
    const float inv_s2 = 1.f / (sigma * sigma);
    const float bgate  = Wgb[0];
    const float gw     = gpw[0];

    float* myW = sScr + wid * 64;
    int*   myI = reinterpret_cast<int*>(myW + 32);

    // ---- epilogue: EXACT rescore + softmax + gathers + gate ----
#pragma unroll
    for (int round = 0; round < 4; ++round) {
        int q   = wid + 8 * round;
        int qg2 = q0 + q;

        int idx = sTopI[q * 32 + lane];

        const float4* mrow = reinterpret_cast<const float4*>(mu + (size_t)idx * DK);
        const float4* qrow = reinterpret_cast<const float4*>(q_tilde + (size_t)qg2 * DK);
        float d0 = 0.f, d1 = 0.f, d2 = 0.f, d3 = 0.f;
#pragma unroll
        for (int j = 0; j < 16; j += 4) {
            float4 m0 = mrow[j],     qv0 = qrow[j];
            float4 m1 = mrow[j + 1], qv1 = qrow[j + 1];
            float4 m2 = mrow[j + 2], qv2 = qrow[j + 2];
            float4 m3 = mrow[j + 3], qv3 = qrow[j + 3];
            d0 += m0.x * qv0.x + m0.y * qv0.y + m0.z * qv0.z + m0.w * qv0.w;
            d1 += m1.x * qv1.x + m1.y * qv1.y + m1.z * qv1.z + m1.w * qv1.w;
            d2 += m2.x * qv2.x + m2.y * qv2.y + m2.z * qv2.z + m2.w * qv2.w;
            d3 += m3.x * qv3.x + m3.y * qv3.y + m3.z * qv3.z + m3.w * qv3.w;
        }
        float s = ((d0 + d1) + (d2 + d3) - g_hm2[idx]) * inv_s2;

        float mx = s;
#pragma unroll
        for (int off = 16; off; off >>= 1)
            mx = fmaxf(mx, __shfl_xor_sync(FULLMASK, mx, off));
        float e = __expf(s - mx);
        float se = e;
#pragma unroll
        for (int off = 16; off; off >>= 1)
            se += __shfl_xor_sync(FULLMASK, se, off);
        float wgt = e / se;

        myW[lane] = wgt;
        myI[lane] = idx;
        __syncwarp();

        float4 acc = make_float4(0.f, 0.f, 0.f, 0.f);
#pragma unroll 4
        for (int k = 0; k < 32; k++) {
            float wk = myW[k];
            size_t row = (size_t)myI[k];
            float4 v = reinterpret_cast<const float4*>(V + row * 128)[lane];
            acc.x += wk * v.x; acc.y += wk * v.y;
            acc.z += wk * v.z; acc.w += wk * v.w;
        }

        float re = 0.f;
        if (lane < 4) {
            for (int k = 0; k < 32; k++)
                re += myW[k] * E[(size_t)myI[k] * 4 + lane];
        }

        const float4 wv = reinterpret_cast<const float4*>(Wg + 256)[lane];
        float tot = acc.x * wv.x + acc.y * wv.y + acc.z * wv.z + acc.w * wv.w;
        const float* xq = x + (size_t)qg2 * 256;
#pragma unroll
        for (int u = 0; u < 8; u++) {
            int t = lane + 32 * u;
            tot += xq[t] * Wg[t];
        }
#pragma unroll
        for (int off = 16; off; off >>= 1)
            tot += __shfl_xor_sync(FULLMASK, tot, off);

        reinterpret_cast<float4*>(out + RV_OFF + (size_t)qg2 * 128)[lane] = acc;
        if (lane < 4) out[RE_OFF + (size_t)qg2 * 4 + lane] = re;
        if (lane == 0) {
            float z = tot + bgate + gw * g_prior[qg2];
            out[G_OFF + qg2] = 1.f / (1.f + __expf(-z));
        }
        __syncwarp();
    }
}

extern "C" void kernel_launch(void* const* d_in, const int* in_sizes, int n_in,
                              void* d_out, int out_size) {
    (void)in_sizes; (void)n_in; (void)out_size;
    const float* x   = (const float*)d_in[0];
    const float* qt  = (const float*)d_in[1];
    const float* gp  = (const float*)d_in[2];
    const float* mu  = (const float*)d_in[3];
    const float* V   = (const float*)d_in[4];
    const float* E   = (const float*)d_in[5];
    const float* sg  = (const float*)d_in[6];
    const float* Wg  = (const float*)d_in[7];
    const float* Wb  = (const float*)d_in[8];
    const float* gw  = (const float*)d_in[9];

    prep_kernel<<<NC / 256, 256>>>(mu);

    const int smem_bytes = SMEM_FLOATS * 4;   // 106560
    cudaFuncSetAttribute(ma_kernel, cudaFuncAttributeMaxDynamicSharedMemorySize,
                         smem_bytes);
    ma_kernel<<<NQ / QT, 256, smem_bytes>>>(x, qt, gp, mu, V, E, sg, Wg, Wb, gw,
                                            (float*)d_out);
}

// round 17
// speedup vs baseline: 1.3132x; 1.1571x over previous
#include <cuda_runtime.h>
#include <cuda_fp16.h>
#include <cstdint>

// ---------------------------------------------------------------------------
// MemoryAttention R17: R16 with the score GEMM in fp16 (m16n8k16, fp32 acc).
//   fp16 mantissa (10 bits) == tf32 mantissa -> identical selection quality,
//   half the instructions:
//     - 16 MMA + 4 LDSM per warp per chunk (was 32 + 8)
//     - mu stored fp16: TMA 18.9KB/chunk (was 35.3KB), blob smem halved
//     - A fragments 32 regs (was 64)
//   B via ldmatrix.x4 non-trans on mu rows (stride 72 halfs = 144B,
//   bank-quads 0,4,..,28 -> conflict-free). D fragment mapping identical to
//   tf32 m16n8k8, so score-store layout, selection, and the exact-fp32
//   rescore epilogue are carried over from R16 unchanged.
// ---------------------------------------------------------------------------

#define FULLMASK 0xffffffffu

constexpr int NQ  = 8192;
constexpr int NC  = 32768;
constexpr int DK  = 64;
constexpr int QT  = 32;        // queries per CTA
constexpr int CT  = 128;       // centers per chunk
constexpr int NCHUNK = NC / CT;    // 256
constexpr int MUS  = 68;       // fp32 Q staging row stride (floats)
constexpr int MUSH = 72;       // fp16 mu row stride (halfs) = 144 B
constexpr int SSTR = 132;      // score row stride
constexpr int SBUF = QT * SSTR;    // floats per score buffer
constexpr int BUFFLOATS = CT + CT * MUSH / 2;   // 128 hm2 + 4608 = 4736
constexpr uint32_t BUFBYTES = BUFFLOATS * 4;    // 18944 B (16B-multiple)

static __device__ float g_hm2[NC];
static __device__ float g_blob[(size_t)NCHUNK * BUFFLOATS];   // ~4.9 MB

constexpr int RV_OFF = 0;
constexpr int RE_OFF = NQ * 128;
constexpr int G_OFF  = RE_OFF + NQ * 4;

// smem layout (floats)
constexpr int OFF_MBAR = 0;                        // 2 mbarriers
constexpr int OFF_BLOB = 16;                       // 2*4736 = 9472
constexpr int OFF_S0   = OFF_BLOB + 2 * BUFFLOATS; // 4224 (sQ aliases here)
constexpr int OFF_S1   = OFF_S0 + SBUF;            // 4224
constexpr int OFF_SCR  = OFF_S1 + SBUF;            // 512
constexpr int SMEM_FLOATS = OFF_SCR + 8 * 64;      // 18448 f = 73792 B

__device__ __forceinline__ uint32_t pkh2(float a, float b) {
    __half2 h = __floats2half2_rn(a, b);
    return *reinterpret_cast<uint32_t*>(&h);
}

__global__ void prep_kernel(const float* __restrict__ mu) {
    int c = blockIdx.x * 256 + threadIdx.x;   // 32768 rows
    const float4* r = reinterpret_cast<const float4*>(mu) + (size_t)c * 16;
    int n = c & 127;
    float* blob = g_blob + (size_t)(c >> 7) * BUFFLOATS;
    uint32_t* hrow = reinterpret_cast<uint32_t*>(
        reinterpret_cast<__half*>(blob + CT) + n * MUSH);
    float s = 0.f;
#pragma unroll
    for (int j = 0; j < 16; j++) {
        float4 v = r[j];
        s += v.x * v.x + v.y * v.y + v.z * v.z + v.w * v.w;
        hrow[2 * j]     = pkh2(v.x, v.y);
        hrow[2 * j + 1] = pkh2(v.z, v.w);
    }
    // hm2 quad layout: thread (w,tc) reads float4 =
    //   { hm2[16w+2tc], hm2[16w+2tc+1], hm2[16w+8+2tc], hm2[16w+8+2tc+1] }
    int w  = n >> 4, inner = n & 15;
    int h  = inner >> 3, rem = inner & 7;
    int tc = rem >> 1, e = rem & 1;
    blob[(w * 4 + tc) * 4 + 2 * h + e] = 0.5f * s;
    g_hm2[c] = 0.5f * s;
}

__device__ __forceinline__ unsigned fenc(float f) {
    unsigned u = __float_as_uint(f);
    return (u & 0x80000000u) ? ~u : (u | 0x80000000u);
}
__device__ __forceinline__ float fdec(unsigned u) {
    return (u & 0x80000000u) ? __uint_as_float(u & 0x7fffffffu)
                             : __uint_as_float(~u);
}
__device__ __forceinline__ unsigned redux_min_u32(unsigned v) {
    unsigned r;
    asm("redux.sync.min.u32 %0, %1, 0xffffffff;" : "=r"(r) : "r"(v));
    return r;
}
__device__ __forceinline__ void mma_f16(float* d, const uint32_t* a,
                                        uint32_t b0, uint32_t b1) {
    asm("mma.sync.aligned.m16n8k16.row.col.f32.f16.f16.f32 "
        "{%0,%1,%2,%3}, {%4,%5,%6,%7}, {%8,%9}, {%0,%1,%2,%3};"
        : "+f"(d[0]), "+f"(d[1]), "+f"(d[2]), "+f"(d[3])
        : "r"(a[0]), "r"(a[1]), "r"(a[2]), "r"(a[3]), "r"(b0), "r"(b1));
}
__device__ __forceinline__ void ldsm_x4(uint32_t addr, uint32_t& r0,
                                        uint32_t& r1, uint32_t& r2, uint32_t& r3) {
    asm volatile("ldmatrix.sync.aligned.m8n8.x4.shared.b16 {%0,%1,%2,%3}, [%4];"
                 : "=r"(r0), "=r"(r1), "=r"(r2), "=r"(r3) : "r"(addr));
}
__device__ __forceinline__ void mbar_init(uint32_t addr, uint32_t count) {
    asm volatile("mbarrier.init.shared.b64 [%0], %1;" :: "r"(addr), "r"(count)
                 : "memory");
}
__device__ __forceinline__ void mbar_expect_tx(uint32_t addr, uint32_t bytes) {
    asm volatile("mbarrier.arrive.expect_tx.shared.b64 _, [%0], %1;"
                 :: "r"(addr), "r"(bytes) : "memory");
}
__device__ __forceinline__ void mbar_wait(uint32_t addr, uint32_t parity) {
    asm volatile(
        "{\n\t"
        ".reg .pred P;\n"
        "W_%=:\n\t"
        "mbarrier.try_wait.parity.acquire.cta.shared::cta.b64 P, [%0], %1, 0x989680;\n\t"
        "@P bra D_%=;\n\t"
        "bra W_%=;\n"
        "D_%=:\n\t"
        "}"
        :: "r"(addr), "r"(parity) : "memory");
}
__device__ __forceinline__ void bulk_g2s(uint32_t dst, const void* src,
                                         uint32_t bytes, uint32_t mbar) {
    asm volatile(
        "cp.async.bulk.shared::cta.global.mbarrier::complete_tx::bytes "
        "[%0], [%1], %2, [%3];"
        :: "r"(dst), "l"(src), "r"(bytes), "r"(mbar) : "memory");
}

__global__ __launch_bounds__(256, 2)
void ma_kernel(const float* __restrict__ x,
               const float* __restrict__ q_tilde,
               const float* __restrict__ g_prior,
               const float* __restrict__ mu,
               const float* __restrict__ V,
               const float* __restrict__ E,
               const float* __restrict__ sig,
               const float* __restrict__ Wg,
               const float* __restrict__ Wgb,
               const float* __restrict__ gpw,
               float* __restrict__ out) {
    extern __shared__ float sm[];
    float* sBlob = sm + OFF_BLOB;
    float* sS    = sm + OFF_S0;     // two score buffers
    float* sQ    = sm + OFF_S0;     // alias: Q staged here only for A-frags
    float* sScr  = sm + OFF_SCR;

    const int tid  = threadIdx.x;
    const int lane = tid & 31;
    const int wid  = tid >> 5;      // warp = column block w (16 cols)
    const int q0   = blockIdx.x * QT;

    const int tr = lane >> 2;     // 0..7  (g)
    const int tc = lane & 3;      // 0..3  (t)

    const uint32_t smemBase = (uint32_t)__cvta_generic_to_shared(sm);
    const uint32_t mbarA  = smemBase + OFF_MBAR * 4;
    const uint32_t sblobA = smemBase + OFF_BLOB * 4;

    // ldmatrix lane offset (bytes) within a blob's fp16 mu section:
    //   matrix lm = lane>>3: rows 16*wid + (lm>>1)*8 + lane&7, k-half (lm&1)
    const int lm = lane >> 3;
    const uint32_t boff = (uint32_t)(CT * 4) +
        (uint32_t)(((16 * wid + (lm >> 1) * 8 + (lane & 7)) * MUSH
                    + (lm & 1) * 8) * 2);

    // hm2 quad word offset
    const int hmoff = 16 * wid + 4 * tc;

    // score store word offsets for the 4 rows R = 16m+8h+tr
    int Wr[2][2];
#pragma unroll
    for (int m = 0; m < 2; m++)
#pragma unroll
        for (int h = 0; h < 2; h++) {
            int R = 16 * m + 8 * h + tr;
            Wr[m][h] = (16 * (wid ^ (R & 1)) + 4 * tc + 2048 - 4 * R) & 127;
        }

    auto issue_chunk = [&](int chunk) {
        if (tid == 0) {
            int buf = chunk & 1;
            uint32_t mb = mbarA + (uint32_t)(buf * 8);
            mbar_expect_tx(mb, BUFBYTES);
            bulk_g2s(sblobA + (uint32_t)buf * BUFBYTES,
                     g_blob + (size_t)chunk * BUFFLOATS, BUFBYTES, mb);
        }
    };

    // ---- prologue: stage Q (aliased region), init mbarriers ----
    for (int idx = tid; idx < QT * DK; idx += 256) {
        int q = idx >> 6, k = idx & 63;
        sQ[q * MUS + k] = q_tilde[(size_t)(q0 + q) * DK + k];
    }
    if (tid == 0) {
        mbar_init(mbarA, 1);
        mbar_init(mbarA + 8, 1);
    }
    __syncthreads();   // sQ + mbarrier init visible
    issue_chunk(0);

    // A fragments fp16 for both m-tiles: af[m][kt][4], kt covers k=16
    uint32_t af[2][4][4];
#pragma unroll
    for (int m = 0; m < 2; m++) {
        const float* qa = sQ + (16 * m + tr) * MUS;       // row g
        const float* qb = qa + 8 * MUS;                   // row g+8
#pragma unroll
        for (int kt = 0; kt < 4; kt++) {
            int k0 = 16 * kt + 2 * tc;
            af[m][kt][0] = pkh2(qa[k0],     qa[k0 + 1]);
            af[m][kt][1] = pkh2(qb[k0],     qb[k0 + 1]);
            af[m][kt][2] = pkh2(qa[k0 + 8], qa[k0 + 9]);
            af[m][kt][3] = pkh2(qb[k0 + 8], qb[k0 + 9]);
        }
    }
    // sQ dead from here; first sS0 write is after the first in-loop barrier.

    // selection state: warp wid owns queries 4*wid + r
    unsigned cu[4]; int ci[4]; float thr[4]; unsigned thrU[4];
    const unsigned NEGINF_U = fenc(-INFINITY);
#pragma unroll
    for (int r = 0; r < 4; r++) {
        cu[r] = NEGINF_U; ci[r] = 0; thr[r] = -INFINITY; thrU[r] = NEGINF_U;
    }

    // deferred selection of one chunk's score tile (reads sbuf)
    auto select_chunk = [&](const float* sbuf, int base) {
        float4 f[4]; float lmax[4];
#pragma unroll
        for (int r = 0; r < 4; r++) {
            const float* row = sbuf + (4 * wid + r) * SSTR;
            f[r] = *reinterpret_cast<const float4*>(row + 4 * lane);
            lmax[r] = fmaxf(fmaxf(f[r].x, f[r].y), fmaxf(f[r].z, f[r].w));
        }
        bool anyc = (lmax[0] > thr[0]) | (lmax[1] > thr[1]) |
                    (lmax[2] > thr[2]) | (lmax[3] > thr[3]);
        if (!__ballot_sync(FULLMASK, anyc)) return;
#pragma unroll
        for (int r = 0; r < 4; r++) {
            const int row = 4 * wid + r;
            unsigned m = __ballot_sync(FULLMASK, lmax[r] > thr[r]);
            while (m) {
                int src = __ffs(m) - 1;
                m &= m - 1;
                float g0 = __shfl_sync(FULLMASK, f[r].x, src);
                float g1 = __shfl_sync(FULLMASK, f[r].y, src);
                float g2 = __shfl_sync(FULLMASK, f[r].z, src);
                float g3 = __shfl_sync(FULLMASK, f[r].w, src);
                // decode stored column: X=(4src+4row)&127; w=(X>>4)^(row&1)
                int X = (4 * src + 4 * row) & 127;
                int wdec = ((X >> 4) ^ (row & 1));
                int colb = 16 * wdec + ((X >> 2) & 3) * 2;
                int ib = base + colb;
#pragma unroll
                for (int j = 0; j < 4; j++) {
                    float nv = (j == 0) ? g0 : (j == 1) ? g1 : (j == 2) ? g2 : g3;
                    if (nv > thr[r]) {
                        unsigned bl = __ballot_sync(FULLMASK, cu[r] == thrU[r]);
                        int ml = __ffs(bl) - 1;
                        if (lane == ml) {
                            cu[r] = fenc(nv);
                            ci[r] = ib + 8 * (j >> 1) + (j & 1);
                        }
                        thrU[r] = redux_min_u32(cu[r]);
                        thr[r]  = fdec(thrU[r]);
                    }
                }
            }
        }
    };

    for (int ch = 0; ch < NCHUNK; ++ch) {
        const int buf = ch & 1;
        __syncthreads();   // orders stores(ch-1), select(ch-2), and all warps'
                           // GEMM(ch-1) reads of buffer buf^1
        if (ch + 1 < NCHUNK) issue_chunk(ch + 1);
        mbar_wait(mbarA + (uint32_t)(buf * 8), (ch >> 1) & 1);

        const uint32_t bufB = sblobA + (uint32_t)buf * BUFBYTES;
        const float*   hbp  = sBlob + buf * BUFFLOATS;

        // ---- tensor-core GEMM: warp tile 32q x 16c, fp16 m16n8k16 ----
        float acc[2][2][4];
#pragma unroll
        for (int m = 0; m < 2; m++)
#pragma unroll
            for (int nt = 0; nt < 2; nt++)
#pragma unroll
                for (int j = 0; j < 4; j++) acc[m][nt][j] = 0.f;

        const uint32_t a0 = bufB + boff;
#pragma unroll
        for (int kt = 0; kt < 4; kt++) {
            uint32_t r0, r1, r2, r3;
            ldsm_x4(a0 + kt * 32, r0, r1, r2, r3);
            mma_f16(acc[0][0], af[0][kt], r0, r1);
            mma_f16(acc[0][1], af[0][kt], r2, r3);
            mma_f16(acc[1][0], af[1][kt], r0, r1);
            mma_f16(acc[1][1], af[1][kt], r2, r3);
        }

        // ---- deferred selection of previous chunk (overlaps GEMM latency) ----
        if (ch > 0)
            select_chunk(sS + ((ch - 1) & 1) * SBUF, (ch - 1) * CT);

        // ---- scores -> sS[ch&1] (row-shifted layout, 4x STS.128) ----
        {
            float* sb = sS + buf * SBUF;
            float4 hm = *reinterpret_cast<const float4*>(hbp + hmoff);
#pragma unroll
            for (int m = 0; m < 2; m++)
#pragma unroll
                for (int h = 0; h < 2; h++) {
                    int R = 16 * m + 8 * h + tr;
                    float4 v;
                    v.x = acc[m][0][2 * h]     - hm.x;
                    v.y = acc[m][0][2 * h + 1] - hm.y;
                    v.z = acc[m][1][2 * h]     - hm.z;
                    v.w = acc[m][1][2 * h + 1] - hm.w;
                    *reinterpret_cast<float4*>(sb + R * SSTR + Wr[m][h]) = v;
                }
        }
    }

    // final chunk's selection
    __syncthreads();
    select_chunk(sS + ((NCHUNK - 1) & 1) * SBUF, (NCHUNK - 1) * CT);

    // publish top-32 indices per query into sS0 (final select read sS1)
    int* sTopI = reinterpret_cast<int*>(sS);
#pragma unroll
    for (int r = 0; r < 4; r++) {
        int q = 4 * wid + r;
        sTopI[q * 32 + lane] = ci[r];
    }
    __syncthreads();

    const float sigma  = sig[0];
    const float inv_s2 = 1.f / (sigma * sigma);
    const float bgate  = Wgb[0];
    const float gw     = gpw[0];

    float* myW = sScr + wid * 64;
    int*   myI = reinterpret_cast<int*>(myW + 32);

    // ---- epilogue: EXACT rescore + softmax + gathers + gate ----
#pragma unroll
    for (int round = 0; round < 4; ++round) {
        int q   = wid + 8 * round;
        int qg2 = q0 + q;

        int idx = sTopI[q * 32 + lane];

        const float4* mrow = reinterpret_cast<const float4*>(mu + (size_t)idx * DK);
        const float4* qrow = reinterpret_cast<const float4*>(q_tilde + (size_t)qg2 * DK);
        float d0 = 0.f, d1 = 0.f, d2 = 0.f, d3 = 0.f;
#pragma unroll
        for (int j = 0; j < 16; j += 4) {
            float4 m0 = mrow[j],     qv0 = qrow[j];
            float4 m1 = mrow[j + 1], qv1 = qrow[j + 1];
            float4 m2 = mrow[j + 2], qv2 = qrow[j + 2];
            float4 m3 = mrow[j + 3], qv3 = qrow[j + 3];
            d0 += m0.x * qv0.x + m0.y * qv0.y + m0.z * qv0.z + m0.w * qv0.w;
            d1 += m1.x * qv1.x + m1.y * qv1.y + m1.z * qv1.z + m1.w * qv1.w;
            d2 += m2.x * qv2.x + m2.y * qv2.y + m2.z * qv2.z + m2.w * qv2.w;
            d3 += m3.x * qv3.x + m3.y * qv3.y + m3.z * qv3.z + m3.w * qv3.w;
        }
        float s = ((d0 + d1) + (d2 + d3) - g_hm2[idx]) * inv_s2;

        float mx = s;
#pragma unroll
        for (int off = 16; off; off >>= 1)
            mx = fmaxf(mx, __shfl_xor_sync(FULLMASK, mx, off));
        float e = __expf(s - mx);
        float se = e;
#pragma unroll
        for (int off = 16; off; off >>= 1)
            se += __shfl_xor_sync(FULLMASK, se, off);
        float wgt = e / se;

        myW[lane] = wgt;
        myI[lane] = idx;
        __syncwarp();

        float4 acc = make_float4(0.f, 0.f, 0.f, 0.f);
#pragma unroll 4
        for (int k = 0; k < 32; k++) {
            float wk = myW[k];
            size_t row = (size_t)myI[k];
            float4 v = reinterpret_cast<const float4*>(V + row * 128)[lane];
            acc.x += wk * v.x; acc.y += wk * v.y;
            acc.z += wk * v.z; acc.w += wk * v.w;
        }

        float re = 0.f;
        if (lane < 4) {
            for (int k = 0; k < 32; k++)
                re += myW[k] * E[(size_t)myI[k] * 4 + lane];
        }

        const float4 wv = reinterpret_cast<const float4*>(Wg + 256)[lane];
        float tot = acc.x * wv.x + acc.y * wv.y + acc.z * wv.z + acc.w * wv.w;
        const float* xq = x + (size_t)qg2 * 256;
#pragma unroll
        for (int u = 0; u < 8; u++) {
            int t = lane + 32 * u;
            tot += xq[t] * Wg[t];
        }
#pragma unroll
        for (int off = 16; off; off >>= 1)
            tot += __shfl_xor_sync(FULLMASK, tot, off);

        reinterpret_cast<float4*>(out + RV_OFF + (size_t)qg2 * 128)[lane] = acc;
        if (lane < 4) out[RE_OFF + (size_t)qg2 * 4 + lane] = re;
        if (lane == 0) {
            float z = tot + bgate + gw * g_prior[qg2];
            out[G_OFF + qg2] = 1.f / (1.f + __expf(-z));
        }
        __syncwarp();
    }
}

extern "C" void kernel_launch(void* const* d_in, const int* in_sizes, int n_in,
                              void* d_out, int out_size) {
    (void)in_sizes; (void)n_in; (void)out_size;
    const float* x   = (const float*)d_in[0];
    const float* qt  = (const float*)d_in[1];
    const float* gp  = (const float*)d_in[2];
    const float* mu  = (const float*)d_in[3];
    const float* V   = (const float*)d_in[4];
    const float* E   = (const float*)d_in[5];
    const float* sg  = (const float*)d_in[6];
    const float* Wg  = (const float*)d_in[7];
    const float* Wb  = (const float*)d_in[8];
    const float* gw  = (const float*)d_in[9];

    prep_kernel<<<NC / 256, 256>>>(mu);

    const int smem_bytes = SMEM_FLOATS * 4;   // 73792
    cudaFuncSetAttribute(ma_kernel, cudaFuncAttributeMaxDynamicSharedMemorySize,
                         smem_bytes);
    ma_kernel<<<NQ / QT, 256, smem_bytes>>>(x, qt, gp, mu, V, E, sg, Wg, Wb, gw,
                                            (float*)d_out);
}